// round 1
// baseline (speedup 1.0000x reference)
#include <cuda_runtime.h>
#include <cstdint>
#include <cstddef>

// Problem constants
#define C_CH 64
#define VIN  4096      // 16^3 input spatial per channel
#define VOUT 262144    // 64^3 output spatial per channel

// Scratch (device globals; no allocation allowed)
__device__ float g_X1[128];     // [n*64+c] sum x
__device__ float g_X2[128];     // [n*64+c] sum x^2
__device__ float g_Wg[4096];    // [c][o] = w_pw[o,c]*gamma[c]
__device__ float g_B[128];      // [n][o] fused bias
__device__ float g_rstd[2];

// ---------- packed f32x2 helpers ----------
#define FMA2(d, a, b, c_) \
    asm("fma.rn.f32x2 %0, %1, %2, %3;" : "=l"(d) : "l"(a), "l"(b), "l"(c_))
#define PACKF2(d, f) \
    asm("mov.b64 %0, {%1, %2};" : "=l"(d) : "r"(__float_as_uint(f)), "r"(__float_as_uint(f)))
#define UNPACKF2(lo, hi, v) do { \
    unsigned int _l, _h; \
    asm("mov.b64 {%0, %1}, %2;" : "=r"(_l), "=r"(_h) : "l"(v)); \
    lo = __uint_as_float(_l); hi = __uint_as_float(_h); \
} while (0)

// ---------- kernel 1: per-(n,c) sums of x and x^2 ----------
__global__ void k_stats(const float* __restrict__ x) {
    __shared__ float s1[256], s2[256];
    const int nc = blockIdx.x;
    const float* p = x + (size_t)nc * VIN;
    float a1 = 0.f, a2 = 0.f;
#pragma unroll
    for (int i = 0; i < 16; ++i) {
        float v = p[threadIdx.x + i * 256];
        a1 += v;
        a2 += v * v;
    }
    s1[threadIdx.x] = a1;
    s2[threadIdx.x] = a2;
    __syncthreads();
    for (int st = 128; st > 0; st >>= 1) {
        if (threadIdx.x < st) {
            s1[threadIdx.x] += s1[threadIdx.x + st];
            s2[threadIdx.x] += s2[threadIdx.x + st];
        }
        __syncthreads();
    }
    if (threadIdx.x == 0) {
        g_X1[nc] = s1[0];
        g_X2[nc] = s2[0];
    }
}

// ---------- kernel 2: closed-form GroupNorm stats + fused weights ----------
__global__ void k_prep(const float* __restrict__ w_ct,
                       const float* __restrict__ b_ct,
                       const float* __restrict__ gamma,
                       const float* __restrict__ beta,
                       const float* __restrict__ w_pw) {
    __shared__ float sS1[64], sS2[64];
    __shared__ float sMean[2], sRstd[2];
    const int tid = threadIdx.x;

    if (tid < 64) {
        float s1 = 0.f, s2 = 0.f;
        for (int t = 0; t < 64; ++t) {
            float w = w_ct[tid * 64 + t];
            s1 += w;
            s2 += w * w;
        }
        sS1[tid] = s1;
        sS2[tid] = s2;
    }
    __syncthreads();

    if (tid < 2) {
        double sy = 0.0, sy2 = 0.0;
        for (int c = 0; c < 64; ++c) {
            double X1 = (double)g_X1[tid * 64 + c];
            double X2 = (double)g_X2[tid * 64 + c];
            double b  = (double)b_ct[c];
            double S1 = (double)sS1[c];
            double S2 = (double)sS2[c];
            sy  += S1 * X1 + (double)VOUT * b;
            sy2 += S2 * X2 + 2.0 * b * S1 * X1 + (double)VOUT * b * b;
        }
        double mean = sy / 16777216.0;                      // C * VOUT
        double var  = sy2 / 16777216.0 - mean * mean;
        double rstd = 1.0 / sqrt(var + 1e-5);
        sMean[tid] = (float)mean;
        sRstd[tid] = (float)rstd;
        g_rstd[tid] = (float)rstd;
    }
    __syncthreads();

    // Wg[c][o] = w_pw[o,c] * gamma[c]
    for (int idx = tid; idx < 4096; idx += blockDim.x) {
        int c = idx >> 6, o = idx & 63;
        g_Wg[idx] = w_pw[o * 64 + c] * gamma[c];
    }

    // B[n][o] = rstd * sum_c Wg[o,c]*(b_c - mean) + sum_c w_pw[o,c]*beta_c
    if (tid < 128) {
        int n = tid >> 6, o = tid & 63;
        float mean = sMean[n], rstd = sRstd[n];
        float acc1 = 0.f, acc2 = 0.f;
        for (int c = 0; c < 64; ++c) {
            float wpc = w_pw[o * 64 + c];
            acc1 += wpc * gamma[c] * (b_ct[c] - mean);
            acc2 += wpc * beta[c];
        }
        g_B[tid] = rstd * acc1 + acc2;
    }
}

// ---------- kernel 3: fused scatter-GEMM ----------
// out[n,o,d*4+i,h*4+j,w*4+k] = rstd_n * sum_c Wg[o,c]*w_ct[c,ijk]*x[n,c,dhw] + B[n,o]
__global__ void __launch_bounds__(256, 2)
k_main(const float* __restrict__ x,
       const float* __restrict__ w_ct,
       float* __restrict__ out) {
    __shared__ float sWg[4096];   // [c][o]
    __shared__ float sWct[4096];  // [c][ij*4+k]
    __shared__ float sX[1024];    // [c][w] (16 w)
    __shared__ float sB[64];

    const int b = blockIdx.x;
    const int n = b >> 8;
    const int d = (b >> 4) & 15;
    const int h = b & 15;
    const int tid = threadIdx.x;

    {
        const float4* gWg4 = (const float4*)g_Wg;
        float4* sWg4 = (float4*)sWg;
        const float4* gWc4 = (const float4*)w_ct;
        float4* sWc4 = (float4*)sWct;
#pragma unroll
        for (int i = 0; i < 4; ++i) {
            sWg4[tid + i * 256] = gWg4[tid + i * 256];
            sWc4[tid + i * 256] = gWc4[tid + i * 256];
        }
        const int c = tid >> 2, wq = tid & 3;
        const float4* gx =
            (const float4*)(x + (size_t)(n * 64 + c) * VIN + d * 256 + h * 16);
        ((float4*)sX)[tid] = gx[wq];
        if (tid < 64) sB[tid] = g_B[n * 64 + tid];
    }
    __syncthreads();

    const float rstd = g_rstd[n];

    const int ijq = tid >> 6;        // which (i,j) of 4 concurrent
    const int l64 = tid & 63;
    const int to  = l64 >> 4;        // o-group: 16 o's
    const int tw  = l64 & 15;        // input w position
    const int ob  = to * 16;

    for (int ijr = 0; ijr < 4; ++ijr) {
        const int ij = ijr * 4 + ijq;

        unsigned long long acc[8][4];
#pragma unroll
        for (int p = 0; p < 8; ++p)
#pragma unroll
            for (int k = 0; k < 4; ++k) acc[p][k] = 0ULL;

#pragma unroll 2
        for (int c = 0; c < 64; ++c) {
            const float xw = sX[c * 16 + tw];
            const float4 wv = *(const float4*)&sWct[c * 64 + ij * 4];
            float t0 = xw * wv.x, t1 = xw * wv.y, t2 = xw * wv.z, t3 = xw * wv.w;
            unsigned long long tt0, tt1, tt2, tt3;
            PACKF2(tt0, t0);
            PACKF2(tt1, t1);
            PACKF2(tt2, t2);
            PACKF2(tt3, t3);

            const ulonglong2* wg = (const ulonglong2*)&sWg[c * 64 + ob];
            ulonglong2 w01 = wg[0], w23 = wg[1], w45 = wg[2], w67 = wg[3];
            unsigned long long wp0 = w01.x, wp1 = w01.y, wp2 = w23.x, wp3 = w23.y;
            unsigned long long wp4 = w45.x, wp5 = w45.y, wp6 = w67.x, wp7 = w67.y;

#define STEP(p, wpr)                        \
            FMA2(acc[p][0], wpr, tt0, acc[p][0]); \
            FMA2(acc[p][1], wpr, tt1, acc[p][1]); \
            FMA2(acc[p][2], wpr, tt2, acc[p][2]); \
            FMA2(acc[p][3], wpr, tt3, acc[p][3]);
            STEP(0, wp0) STEP(1, wp1) STEP(2, wp2) STEP(3, wp3)
            STEP(4, wp4) STEP(5, wp5) STEP(6, wp6) STEP(7, wp7)
#undef STEP
        }

        // epilogue: scale by rstd, add fused bias, scattered float4 stores
        const int i = ij >> 2, j = ij & 3;
        const int dout = d * 4 + i;
        const int hout = h * 4 + j;
        const size_t sbase =
            (size_t)(n * 64) * VOUT + (size_t)dout * 4096 + (size_t)hout * 64 + tw * 4;

#pragma unroll
        for (int p = 0; p < 8; ++p) {
            float lo0, hi0, lo1, hi1, lo2, hi2, lo3, hi3;
            UNPACKF2(lo0, hi0, acc[p][0]);
            UNPACKF2(lo1, hi1, acc[p][1]);
            UNPACKF2(lo2, hi2, acc[p][2]);
            UNPACKF2(lo3, hi3, acc[p][3]);
            const int o0 = ob + 2 * p;
            const int o1 = o0 + 1;
            const float B0 = sB[o0], B1 = sB[o1];
            float4 r0, r1;
            r0.x = fmaf(rstd, lo0, B0);
            r0.y = fmaf(rstd, lo1, B0);
            r0.z = fmaf(rstd, lo2, B0);
            r0.w = fmaf(rstd, lo3, B0);
            r1.x = fmaf(rstd, hi0, B1);
            r1.y = fmaf(rstd, hi1, B1);
            r1.z = fmaf(rstd, hi2, B1);
            r1.w = fmaf(rstd, hi3, B1);
            *(float4*)&out[sbase + (size_t)o0 * VOUT] = r0;
            *(float4*)&out[sbase + (size_t)o1 * VOUT] = r1;
        }
    }
}

extern "C" void kernel_launch(void* const* d_in, const int* in_sizes, int n_in,
                              void* d_out, int out_size) {
    const float* x     = (const float*)d_in[0];
    const float* w_ct  = (const float*)d_in[1];
    const float* b_ct  = (const float*)d_in[2];
    const float* gamma = (const float*)d_in[3];
    const float* beta  = (const float*)d_in[4];
    const float* w_pw  = (const float*)d_in[5];
    float* out = (float*)d_out;

    k_stats<<<128, 256>>>(x);
    k_prep<<<1, 256>>>(w_ct, b_ct, gamma, beta, w_pw);
    k_main<<<512, 256>>>(x, w_ct, out);
}

// round 4
// speedup vs baseline: 1.3471x; 1.3471x over previous
#include <cuda_runtime.h>
#include <cstdint>
#include <cstddef>

#define VIN  4096      // 16^3
#define VOUT 262144    // 64^3
#define WPAD 72        // padded row stride (floats / bf16 elems) to kill bank conflicts

// ---------------- device scratch (no allocation allowed) ----------------
__device__ float g_X1[128];   // [n*64+c] sum x
__device__ float g_X2[128];   // [n*64+c] sum x^2
__device__ __align__(16) unsigned short g_WgHi[64 * WPAD];  // bf16 hi of Wg[o][c], padded rows
__device__ __align__(16) unsigned short g_WgLo[64 * WPAD];  // bf16 lo residual
__device__ float g_B[128];    // [n][o] fused bias
__device__ float g_rstd[2];

// ---------------- helpers ----------------
__device__ __forceinline__ uint32_t smem_u32(const void* p) {
    uint32_t a;
    asm("{ .reg .u64 t; cvta.to.shared.u64 t, %1; cvt.u32.u64 %0, t; }" : "=r"(a) : "l"(p));
    return a;
}
__device__ __forceinline__ uint32_t bf16_rne(float v) {
    uint32_t u = __float_as_uint(v);
    return (u + 0x7fffu + ((u >> 16) & 1u)) >> 16;
}
// pack two floats -> bf16x2 (lo = p0, hi = p1), round-to-nearest-even
__device__ __forceinline__ uint32_t cvt_bf16x2(float p0, float p1) {
    uint32_t r;
    asm("cvt.rn.bf16x2.f32 %0, %1, %2;" : "=r"(r) : "f"(p1), "f"(p0));
    return r;
}
__device__ __forceinline__ void mma_bf16(float* c, const uint32_t* a, uint32_t b0, uint32_t b1) {
    asm volatile(
        "mma.sync.aligned.m16n8k16.row.col.f32.bf16.bf16.f32 "
        "{%0,%1,%2,%3}, {%4,%5,%6,%7}, {%8,%9}, {%0,%1,%2,%3};"
        : "+f"(c[0]), "+f"(c[1]), "+f"(c[2]), "+f"(c[3])
        : "r"(a[0]), "r"(a[1]), "r"(a[2]), "r"(a[3]), "r"(b0), "r"(b1));
}
__device__ __forceinline__ void ldmat_x4(uint32_t* r, uint32_t addr) {
    asm volatile("ldmatrix.sync.aligned.m8n8.x4.shared.b16 {%0,%1,%2,%3}, [%4];"
                 : "=r"(r[0]), "=r"(r[1]), "=r"(r[2]), "=r"(r[3]) : "r"(addr));
}

// ---------------- kernel 1: per-(n,c) sums ----------------
__global__ void k_stats(const float* __restrict__ x) {
    const int nc = blockIdx.x;
    const float4* p = (const float4*)(x + (size_t)nc * VIN);
    float a1 = 0.f, a2 = 0.f;
#pragma unroll
    for (int i = 0; i < 4; ++i) {
        float4 v = p[threadIdx.x + i * 256];
        a1 += v.x + v.y + v.z + v.w;
        a2 += v.x * v.x + v.y * v.y + v.z * v.z + v.w * v.w;
    }
#pragma unroll
    for (int off = 16; off; off >>= 1) {
        a1 += __shfl_xor_sync(0xffffffffu, a1, off);
        a2 += __shfl_xor_sync(0xffffffffu, a2, off);
    }
    __shared__ float s1[8], s2[8];
    int wid = threadIdx.x >> 5, lid = threadIdx.x & 31;
    if (lid == 0) { s1[wid] = a1; s2[wid] = a2; }
    __syncthreads();
    if (threadIdx.x == 0) {
        float t1 = 0.f, t2 = 0.f;
        for (int w = 0; w < 8; ++w) { t1 += s1[w]; t2 += s2[w]; }
        g_X1[nc] = t1;
        g_X2[nc] = t2;
    }
}

// ---------------- kernel 2: closed-form stats + split weights ----------------
__global__ void k_prep(const float* __restrict__ w_ct,
                       const float* __restrict__ b_ct,
                       const float* __restrict__ gamma,
                       const float* __restrict__ beta,
                       const float* __restrict__ w_pw) {
    __shared__ float sS1[64], sS2[64];
    __shared__ float sMean[2], sRstd[2];
    const int tid = threadIdx.x;

    if (tid < 64) {
        float s1 = 0.f, s2 = 0.f;
        for (int t = 0; t < 64; ++t) {
            float w = w_ct[tid * 64 + t];
            s1 += w;
            s2 += w * w;
        }
        sS1[tid] = s1;
        sS2[tid] = s2;
    }
    __syncthreads();

    if (tid < 2) {
        double sy = 0.0, sy2 = 0.0;
        for (int c = 0; c < 64; ++c) {
            double X1 = (double)g_X1[tid * 64 + c];
            double X2 = (double)g_X2[tid * 64 + c];
            double b  = (double)b_ct[c];
            double S1 = (double)sS1[c];
            double S2 = (double)sS2[c];
            sy  += S1 * X1 + (double)VOUT * b;
            sy2 += S2 * X2 + 2.0 * b * S1 * X1 + (double)VOUT * b * b;
        }
        double mean = sy / 16777216.0;
        double var  = sy2 / 16777216.0 - mean * mean;
        double rstd = 1.0 / sqrt(var + 1e-5);
        sMean[tid] = (float)mean;
        sRstd[tid] = (float)rstd;
        g_rstd[tid] = (float)rstd;
    }
    __syncthreads();

    // Wg[o][c] = w_pw[o,c]*gamma[c], split to bf16 hi/lo, padded rows
    for (int idx = tid; idx < 4096; idx += 256) {
        int o = idx >> 6, c = idx & 63;
        float v = w_pw[o * 64 + c] * gamma[c];
        uint32_t hb = bf16_rne(v);
        float hv = __uint_as_float(hb << 16);
        uint32_t lb = bf16_rne(v - hv);
        g_WgHi[o * WPAD + c] = (unsigned short)hb;
        g_WgLo[o * WPAD + c] = (unsigned short)lb;
    }
    // zero padding columns so copies are deterministic
    for (int idx = tid; idx < 64 * 8; idx += 256) {
        int o = idx >> 3, c = 64 + (idx & 7);
        g_WgHi[o * WPAD + c] = 0;
        g_WgLo[o * WPAD + c] = 0;
    }

    if (tid < 128) {
        int n = tid >> 6, o = tid & 63;
        float mean = sMean[n], rstd = sRstd[n];
        float acc1 = 0.f, acc2 = 0.f;
        for (int c = 0; c < 64; ++c) {
            float wpc = w_pw[o * 64 + c];
            acc1 += wpc * gamma[c] * (b_ct[c] - mean);
            acc2 += wpc * beta[c];
        }
        g_B[tid] = rstd * acc1 + acc2;
    }
}

// ---------------- kernel 3: HMMA split-bf16 scatter-GEMM ----------------
// Block = (n, dout, h): D[o=64][s=256] = Wg[64x64] x z[64x256],
// z[c][s] = w_ct[c, i, s>>6, (s&3)] * x[n, c, d, h, (s&63)>>2]
// out[n, o, dout, 4h + s>>6, s&63] = rstd * D + B[n][o]   (spatial offset = h*256 + s)
__global__ void __launch_bounds__(256, 2)
k_main(const float* __restrict__ x,
       const float* __restrict__ w_ct,
       float* __restrict__ out) {
    __shared__ __align__(16) unsigned short sWgHi[64 * WPAD];
    __shared__ __align__(16) unsigned short sWgLo[64 * WPAD];
    __shared__ __align__(16) float sXT[16 * WPAD];   // [w][c] padded
    __shared__ __align__(16) float sWT[16 * WPAD];   // [jk][c] padded (i fixed)
    __shared__ float sB[64];

    const int tid = threadIdx.x;
    const int warp = tid >> 5;
    const int l = tid & 31;

    const int b = blockIdx.x;
    const int n = b >> 10;
    const int dout = (b >> 4) & 63;
    const int h = b & 15;
    const int d = dout >> 2, i = dout & 3;

    // ---- stage operands ----
    {
        const uint4* gh = (const uint4*)g_WgHi;
        const uint4* gl = (const uint4*)g_WgLo;
        uint4* sh = (uint4*)sWgHi;
        uint4* sl = (uint4*)sWgLo;
        for (int idx = tid; idx < 576; idx += 256) {  // 64*72*2B / 16B
            sh[idx] = gh[idx];
            sl[idx] = gl[idx];
        }
        const int c = tid >> 2, q = tid & 3;
        float4 xv = *(const float4*)(x + (size_t)(n * 64 + c) * VIN + d * 256 + h * 16 + q * 4);
        sXT[(q * 4 + 0) * WPAD + c] = xv.x;
        sXT[(q * 4 + 1) * WPAD + c] = xv.y;
        sXT[(q * 4 + 2) * WPAD + c] = xv.z;
        sXT[(q * 4 + 3) * WPAD + c] = xv.w;
        float4 wv = *(const float4*)(w_ct + c * 64 + i * 16 + q * 4);
        sWT[(q * 4 + 0) * WPAD + c] = wv.x;
        sWT[(q * 4 + 1) * WPAD + c] = wv.y;
        sWT[(q * 4 + 2) * WPAD + c] = wv.z;
        sWT[(q * 4 + 3) * WPAD + c] = wv.w;
        if (tid < 64) sB[tid] = g_B[n * 64 + tid];
    }
    __syncthreads();

    const float rstd = g_rstd[n];

    // per-warp column slab: s = warp*32 + nt*8 + (l>>2)
    const int sBase = warp * 32;
    const int lq = l >> 2;
    int xrow[4], wrow[4];
#pragma unroll
    for (int nt = 0; nt < 4; ++nt) {
        int s = sBase + nt * 8 + lq;
        int wout = s & 63;
        xrow[nt] = (wout >> 2) * (WPAD / 2);                   // float2 row base
        wrow[nt] = ((s >> 6) * 4 + (wout & 3)) * (WPAD / 2);
    }
    const float2* xt2 = (const float2*)sXT;
    const float2* wt2 = (const float2*)sWT;

    float acc[4][4][4];
#pragma unroll
    for (int mt = 0; mt < 4; ++mt)
#pragma unroll
        for (int nt = 0; nt < 4; ++nt)
#pragma unroll
            for (int r = 0; r < 4; ++r) acc[mt][nt][r] = 0.f;

    // A-fragment ldmatrix addressing: row = l&15, col-half = (l>>4)*8
    const uint32_t aBaseHi = smem_u32(sWgHi);
    const uint32_t aBaseLo = smem_u32(sWgLo);
    const int o_lm = l & 15;
    const int c_lm = (l & 16) >> 1;

#pragma unroll
    for (int kc = 0; kc < 4; ++kc) {
        uint32_t aHi[4][4], aLo[4][4];
#pragma unroll
        for (int mt = 0; mt < 4; ++mt) {
            uint32_t off = (uint32_t)(((mt * 16 + o_lm) * WPAD + kc * 16 + c_lm) * 2);
            ldmat_x4(aHi[mt], aBaseHi + off);
            ldmat_x4(aLo[mt], aBaseLo + off);
        }
        const int cp = kc * 8 + (l & 3);
#pragma unroll
        for (int nt = 0; nt < 4; ++nt) {
            float2 x0 = xt2[xrow[nt] + cp];
            float2 w0 = wt2[wrow[nt] + cp];
            float2 x1 = xt2[xrow[nt] + cp + 4];
            float2 w1 = wt2[wrow[nt] + cp + 4];
            float p0 = x0.x * w0.x, p1 = x0.y * w0.y;
            float p2 = x1.x * w1.x, p3 = x1.y * w1.y;
            uint32_t b0h = cvt_bf16x2(p0, p1);
            uint32_t b1h = cvt_bf16x2(p2, p3);
            float r0 = p0 - __uint_as_float(b0h << 16);
            float r1 = p1 - __uint_as_float(b0h & 0xffff0000u);
            float r2 = p2 - __uint_as_float(b1h << 16);
            float r3 = p3 - __uint_as_float(b1h & 0xffff0000u);
            uint32_t b0l = cvt_bf16x2(r0, r1);
            uint32_t b1l = cvt_bf16x2(r2, r3);
#pragma unroll
            for (int mt = 0; mt < 4; ++mt) {
                mma_bf16(acc[mt][nt], aHi[mt], b0h, b1h);  // hi*hi
                mma_bf16(acc[mt][nt], aHi[mt], b0l, b1l);  // hi*lo
                mma_bf16(acc[mt][nt], aLo[mt], b0h, b1h);  // lo*hi
            }
        }
    }

    // ---- epilogue: rstd scale + fused bias, coalesced float2 stores ----
    const size_t outBase = (size_t)n * 64 * VOUT + (size_t)dout * 4096 + (size_t)h * 256;
#pragma unroll
    for (int mt = 0; mt < 4; ++mt) {
        const int o0 = mt * 16 + (l >> 2);
        const int o1 = o0 + 8;
        const float B0 = sB[o0], B1 = sB[o1];
        float* p0 = out + outBase + (size_t)o0 * VOUT;
        float* p1 = out + outBase + (size_t)o1 * VOUT;
#pragma unroll
        for (int nt = 0; nt < 4; ++nt) {
            const int s = sBase + nt * 8 + 2 * (l & 3);
            float2 v0, v1;
            v0.x = fmaf(rstd, acc[mt][nt][0], B0);
            v0.y = fmaf(rstd, acc[mt][nt][1], B0);
            v1.x = fmaf(rstd, acc[mt][nt][2], B1);
            v1.y = fmaf(rstd, acc[mt][nt][3], B1);
            *(float2*)(p0 + s) = v0;
            *(float2*)(p1 + s) = v1;
        }
    }
}

extern "C" void kernel_launch(void* const* d_in, const int* in_sizes, int n_in,
                              void* d_out, int out_size) {
    (void)in_sizes; (void)n_in; (void)out_size;
    const float* x     = (const float*)d_in[0];
    const float* w_ct  = (const float*)d_in[1];
    const float* b_ct  = (const float*)d_in[2];
    const float* gamma = (const float*)d_in[3];
    const float* beta  = (const float*)d_in[4];
    const float* w_pw  = (const float*)d_in[5];
    float* out = (float*)d_out;

    k_stats<<<128, 256>>>(x);
    k_prep<<<1, 256>>>(w_ct, b_ct, gamma, beta, w_pw);
    k_main<<<2048, 256>>>(x, w_ct, out);
}